// round 12
// baseline (speedup 1.0000x reference)
#include <cuda_runtime.h>
#include <cuda_fp16.h>
#include <cstdint>

#define NN 100000
#define EE 1600000
#define DD 128
#define SCAN_T 1024
#define CHUNK  98      // ceil(NN / SCAN_T)

// ---------------- scratch (no allocations allowed) ----------------
__device__ uint2  g_xh  [(size_t)NN * 32];  // fp16 in_feat / layer-1 input
__device__ uint2  g_h1h [(size_t)NN * 32];  // fp16 h1
__device__ uint2  g_aggh[(size_t)NN * 32];  // fp16 neighbor mean
__device__ __half g_wt1 [128 * 256];        // layer-1 Wt[n][k] fp16, stacked [Ws|Wn]
__device__ __half g_wt2 [128 * 256];        // layer-2
__device__ int    g_cnt[NN];
__device__ int    g_off[NN + 1];
__device__ int    g_cur[NN];
__device__ int    g_csr[EE];

// ---------------- CSR build ----------------
__global__ void zero_cnt_kernel(int* __restrict__ cnt) {
    int i = blockIdx.x * blockDim.x + threadIdx.x;
    if (i < NN) cnt[i] = 0;
}

__global__ void hist_kernel(const int* __restrict__ dst, int* __restrict__ cnt, int E) {
    int e = blockIdx.x * blockDim.x + threadIdx.x;
    if (e < E) atomicAdd(&cnt[dst[e]], 1);
}

__global__ __launch_bounds__(SCAN_T) void scan_kernel(const int* __restrict__ cnt,
                                                      int* __restrict__ off,
                                                      int* __restrict__ cur) {
    __shared__ int ssum[SCAN_T];
    int t = threadIdx.x;
    int start = t * CHUNK;
    int s = 0;
    for (int i = 0; i < CHUNK; i++) {
        int idx = start + i;
        if (idx < NN) s += cnt[idx];
    }
    ssum[t] = s;
    __syncthreads();
    for (int d = 1; d < SCAN_T; d <<= 1) {
        int v = (t >= d) ? ssum[t - d] : 0;
        __syncthreads();
        ssum[t] += v;
        __syncthreads();
    }
    int running = (t == 0) ? 0 : ssum[t - 1];
    for (int i = 0; i < CHUNK; i++) {
        int idx = start + i;
        if (idx < NN) {
            off[idx] = running;
            cur[idx] = running;
            running += cnt[idx];
        }
    }
    if (t == SCAN_T - 1) off[NN] = running;
}

__global__ void fill_kernel(const int* __restrict__ src, const int* __restrict__ dst,
                            int* __restrict__ cur, int* __restrict__ csr, int E) {
    int e = blockIdx.x * blockDim.x + threadIdx.x;
    if (e < E) {
        int pos = atomicAdd(&cur[dst[e]], 1);
        csr[pos] = src[e];
    }
}

// ---------------- fp32 -> fp16 feature convert ----------------
__global__ void cvt_kernel(const float4* __restrict__ x4, uint2* __restrict__ xh, int n4) {
    int i = blockIdx.x * blockDim.x + threadIdx.x;
    if (i >= n4) return;
    float4 v = __ldg(&x4[i]);
    __half2 a = __floats2half2_rn(v.x, v.y);
    __half2 b = __floats2half2_rn(v.z, v.w);
    uint2 o;
    o.x = *(uint32_t*)&a;
    o.y = *(uint32_t*)&b;
    xh[i] = o;
}

// ---------------- W pre-transpose: Wt[n][k] = W[k][n], fp16, stacked ----------------
__global__ void wprep_kernel(const float* __restrict__ Ws, const float* __restrict__ Wn,
                             __half* __restrict__ wt) {
    __shared__ float tile[32][33];
    int k0 = blockIdx.x * 32, n0 = blockIdx.y * 32;
    int w  = blockIdx.z;                   // 0 = Ws, 1 = Wn
    const float* W = w ? Wn : Ws;
    int tx = threadIdx.x, ty = threadIdx.y;   // (32, 8)
    #pragma unroll
    for (int i = ty; i < 32; i += 8)
        tile[i][tx] = __ldg(&W[(k0 + i) * 128 + n0 + tx]);   // coalesced read (n contig)
    __syncthreads();
    #pragma unroll
    for (int i = ty; i < 32; i += 8)
        wt[(n0 + i) * 256 + w * 128 + k0 + tx] =
            __float2half_rn(tile[tx][i]);                     // coalesced write (k contig)
}

// ---------------- mean gather: uint4 lanes, 2 edges per load, fully predicated ----------------
__global__ __launch_bounds__(256) void gather_kernel(
    const uint4* __restrict__ xh,    // [N][16] fp16 rows (16B chunks)
    const int* __restrict__ off,     // [N+1]
    const int* __restrict__ csr,     // [E]
    uint4* __restrict__ aggh)        // [N][16] <- mean (fp16)
{
    int gw = (blockIdx.x * blockDim.x + threadIdx.x) >> 5;   // node id
    if (gw >= NN) return;
    const int lane = threadIdx.x & 31;
    const int half = lane >> 4;          // which edge of the pair
    const int sub  = lane & 15;          // 16B chunk within the row
    int beg = __ldg(&off[gw]);
    int end = __ldg(&off[gw + 1]);

    float acc[8];
    #pragma unroll
    for (int q = 0; q < 8; q++) acc[q] = 0.f;

    // 8 edges per iteration: lane-half h handles edges j+2i+h (i=0..3), 4 uint4 loads/lane
    #pragma unroll 1
    for (int j = beg; j < end; j += 8) {
        #pragma unroll
        for (int i = 0; i < 4; i++) {
            int e = j + 2 * i + half;
            bool valid = e < end;
            int s = __ldg(&csr[valid ? e : beg]);
            uint4 u = __ldg(&xh[(size_t)s * 16 + sub]);
            if (valid) {
                const __half2* h2 = (const __half2*)&u;
                #pragma unroll
                for (int q = 0; q < 4; q++) {
                    float2 f = __half22float2(h2[q]);
                    acc[2 * q]     += f.x;
                    acc[2 * q + 1] += f.y;
                }
            }
        }
    }

    // combine the two half-warps (even/odd edges)
    #pragma unroll
    for (int q = 0; q < 8; q++)
        acc[q] += __shfl_xor_sync(0xffffffffu, acc[q], 16);

    float inv = 1.0f / fmaxf((float)(end - beg), 1.0f);
    if (half == 0) {
        __half2 h[4];
        #pragma unroll
        for (int q = 0; q < 4; q++)
            h[q] = __floats2half2_rn(acc[2 * q] * inv, acc[2 * q + 1] * inv);
        aggh[(size_t)gw * 16 + sub] = *(uint4*)h;
    }
}

// ======================= fp16 mma.sync GEMM layer =======================
// out[0:N,0:128] = relu?( [x | mean] @ Wt^T + b )   (K = 256, fp16 in, fp32 accum)
// Tile: 128 nodes x 128 cols, 8 warps 4x2 (warp: 32 rows x 64 cols), m16n8k16.

#define MMA_F16(c, a, b)                                                         \
    asm volatile("mma.sync.aligned.m16n8k16.row.col.f32.f16.f16.f32 "            \
                 "{%0,%1,%2,%3}, {%4,%5,%6,%7}, {%8,%9}, {%0,%1,%2,%3};"         \
                 : "+f"((c)[0]), "+f"((c)[1]), "+f"((c)[2]), "+f"((c)[3])        \
                 : "r"((a)[0]), "r"((a)[1]), "r"((a)[2]), "r"((a)[3]),           \
                   "r"((b)[0]), "r"((b)[1]))

#define ASTRIDE_H 136   // halves per A row (68 words, 68%32==4 -> conflict-free frags)
#define BSTRIDE_H 264   // halves per B row (132 words, 132%32==4), k=0..255
#define BIAS_BYTES 512
#define AS_BYTES  (128 * ASTRIDE_H * 2)               // 34816
#define BS_OFF_B  (BIAS_BYTES + AS_BYTES)             // 35328
#define SM_BYTES  (BS_OFF_B + 128 * BSTRIDE_H * 2)    // 102912

__global__ __launch_bounds__(256, 2) void layer_mma_kernel(
    const uint2* __restrict__ selfh, // [N][32] fp16 self features
    const uint2* __restrict__ aggh,  // [N][32] fp16 neighbor mean
    const __half* __restrict__ wt,   // [128 n][256 k] fp16 pre-transposed stacked W
    const float* __restrict__ bias,  // [128] fp32
    float* __restrict__ out_f,       // [N,128] fp32 (or nullptr)
    __half* __restrict__ out_h,      // [N,128] fp16 (or nullptr)
    int do_relu)
{
    extern __shared__ char smem[];
    float*  bsm = (float*)smem;                       // [128]
    __half* As  = (__half*)(smem + BIAS_BYTES);       // [128][ASTRIDE_H]
    __half* Bs  = (__half*)(smem + BS_OFF_B);         // [128 n][BSTRIDE_H]
    const int tid = threadIdx.x;
    const int wid = tid >> 5, lane = tid & 31;
    const int g = lane >> 2, tg = lane & 3;
    const int warp_m = wid & 3, warp_n = wid >> 2;
    const int base = blockIdx.x * 128;

    if (tid < 128) bsm[tid] = __ldg(&bias[tid]);

    // ---- stage B: straight uint4 copy of Wt (coalesced LDG, conflict-free STS) ----
    {
        const uint4* wt4 = (const uint4*)wt;          // 4096 uint4 (8 halves each)
        #pragma unroll
        for (int idx = tid; idx < 4096; idx += 256) {
            int n = idx >> 5, kq = idx & 31;          // kq: 8-half chunk along k
            *(uint4*)&Bs[n * BSTRIDE_H + kq * 8] = __ldg(&wt4[idx]);
        }
    }

    float c[2][8][4];
    #pragma unroll
    for (int mt = 0; mt < 2; mt++)
        #pragma unroll
        for (int nt = 0; nt < 8; nt++)
            #pragma unroll
            for (int q = 0; q < 4; q++) c[mt][nt][q] = 0.f;

    // ---- two K-passes: pass0 = self (k 0..127), pass1 = mean (k 128..255) ----
    #pragma unroll 1
    for (int pass = 0; pass < 2; pass++) {
        const uint4* srcA = (const uint4*)(pass ? aggh : selfh);  // 16B = 8 halves
        __syncthreads();   // previous-pass readers done before As overwrite
        #pragma unroll 8
        for (int idx = tid; idx < 2048; idx += 256) {     // 128 rows x 16 uint4
            int r = idx >> 4, q = idx & 15;
            int node = base + r;
            uint4 v = make_uint4(0u, 0u, 0u, 0u);
            if (node < NN) v = __ldg(&srcA[(size_t)node * 16 + q]);
            *(uint4*)&As[r * ASTRIDE_H + q * 8] = v;
        }
        __syncthreads();

        const __half* arow = &As[(warp_m * 32 + g) * ASTRIDE_H + 2 * tg];
        const __half* brow = &Bs[(warp_n * 64 + g) * BSTRIDE_H + 2 * tg + pass * 128];

        #pragma unroll
        for (int ks = 0; ks < 8; ks++) {                  // K = 128 per pass, k16 steps
            const int kb = ks * 16;
            uint32_t a[2][4];
            #pragma unroll
            for (int mt = 0; mt < 2; mt++) {
                const __half* p = arow + mt * 16 * ASTRIDE_H + kb;
                a[mt][0] = *(const uint32_t*)(p);
                a[mt][1] = *(const uint32_t*)(p + 8 * ASTRIDE_H);
                a[mt][2] = *(const uint32_t*)(p + 8);
                a[mt][3] = *(const uint32_t*)(p + 8 * ASTRIDE_H + 8);
            }
            uint32_t b[8][2];
            #pragma unroll
            for (int nt = 0; nt < 8; nt++) {
                const __half* p = brow + nt * 8 * BSTRIDE_H + kb;
                b[nt][0] = *(const uint32_t*)(p);
                b[nt][1] = *(const uint32_t*)(p + 8);
            }
            #pragma unroll
            for (int mt = 0; mt < 2; mt++)
                #pragma unroll
                for (int nt = 0; nt < 8; nt++)
                    MMA_F16(c[mt][nt], a[mt], b[nt]);
        }
    }

    // ---- epilogue: bias (+relu), fp32 and/or fp16 stores ----
    #pragma unroll
    for (int mt = 0; mt < 2; mt++) {
        #pragma unroll
        for (int half = 0; half < 2; half++) {
            int row = warp_m * 32 + mt * 16 + half * 8 + g;
            int node = base + row;
            if (node < NN) {
                #pragma unroll
                for (int nt = 0; nt < 8; nt++) {
                    int col = warp_n * 64 + nt * 8 + tg * 2;
                    float v0 = c[mt][nt][half * 2 + 0] + bsm[col];
                    float v1 = c[mt][nt][half * 2 + 1] + bsm[col + 1];
                    if (do_relu) { v0 = fmaxf(v0, 0.f); v1 = fmaxf(v1, 0.f); }
                    if (out_f)
                        *(float2*)(out_f + (size_t)node * 128 + col) = make_float2(v0, v1);
                    if (out_h) {
                        __half2 h = __floats2half2_rn(v0, v1);
                        *(__half2*)(out_h + (size_t)node * 128 + col) = h;
                    }
                }
            }
        }
    }
}

// ---------------- launch ----------------
extern "C" void kernel_launch(void* const* d_in, const int* in_sizes, int n_in,
                              void* d_out, int out_size) {
    const float* in_feat  = (const float*)d_in[0];
    const float* W1_self  = (const float*)d_in[1];
    const float* W1_neigh = (const float*)d_in[2];
    const float* b1       = (const float*)d_in[3];
    const float* W2_self  = (const float*)d_in[4];
    const float* W2_neigh = (const float*)d_in[5];
    const float* b2       = (const float*)d_in[6];
    const int*   src      = (const int*)d_in[7];
    const int*   dst      = (const int*)d_in[8];
    const int E = in_sizes[7];

    float* out = (float*)d_out;

    uint2 *xh, *h1h, *aggh;
    __half *wt1, *wt2;
    int *cnt, *off, *cur, *csr;
    cudaGetSymbolAddress((void**)&xh,   g_xh);
    cudaGetSymbolAddress((void**)&h1h,  g_h1h);
    cudaGetSymbolAddress((void**)&aggh, g_aggh);
    cudaGetSymbolAddress((void**)&wt1,  g_wt1);
    cudaGetSymbolAddress((void**)&wt2,  g_wt2);
    cudaGetSymbolAddress((void**)&cnt,  g_cnt);
    cudaGetSymbolAddress((void**)&off,  g_off);
    cudaGetSymbolAddress((void**)&cur,  g_cur);
    cudaGetSymbolAddress((void**)&csr,  g_csr);

    cudaFuncSetAttribute(layer_mma_kernel, cudaFuncAttributeMaxDynamicSharedMemorySize, SM_BYTES);

    const int nb = (NN + 255) / 256;
    const int eb = (E + 255) / 256;
    const int gb = (NN * 32 + 255) / 256;     // warp per node
    const int cb = (NN * 32 + 255) / 256;
    const int lb = (NN + 127) / 128;          // 128-node tiles
    dim3 wgrid(4, 4, 2), wblk(32, 8);

    // ---- independent prep first (W transpose + feature cvt), then CSR ----
    wprep_kernel<<<wgrid, wblk>>>(W1_self, W1_neigh, wt1);
    wprep_kernel<<<wgrid, wblk>>>(W2_self, W2_neigh, wt2);
    cvt_kernel<<<cb, 256>>>((const float4*)in_feat, xh, NN * 32);
    zero_cnt_kernel<<<nb, 256>>>(cnt);
    hist_kernel<<<eb, 256>>>(dst, cnt, E);
    scan_kernel<<<1, SCAN_T>>>(cnt, off, cur);
    fill_kernel<<<eb, 256>>>(src, dst, cur, csr, E);

    // ---- layer 1 ----
    gather_kernel<<<gb, 256>>>((const uint4*)xh, off, csr, (uint4*)aggh);
    layer_mma_kernel<<<lb, 256, SM_BYTES>>>(xh, aggh, wt1, b1,
                                            nullptr, (__half*)h1h, 1);

    // ---- layer 2 ----
    gather_kernel<<<gb, 256>>>((const uint4*)h1h, off, csr, (uint4*)aggh);
    layer_mma_kernel<<<lb, 256, SM_BYTES>>>(h1h, aggh, wt2, b2,
                                            out, nullptr, 0);
}

// round 13
// speedup vs baseline: 1.0762x; 1.0762x over previous
#include <cuda_runtime.h>
#include <cuda_fp16.h>
#include <cstdint>

#define NN 100000
#define EE 1600000
#define DD 128
#define SCAN_T 1024
#define CHUNK  98      // ceil(NN / SCAN_T)

// ---------------- scratch (no allocations allowed) ----------------
__device__ uint2  g_xh  [(size_t)NN * 32];  // fp16 in_feat / layer-1 input
__device__ uint2  g_h1h [(size_t)NN * 32];  // fp16 h1
__device__ uint2  g_aggh[(size_t)NN * 32];  // fp16 neighbor mean
__device__ __half g_wt1 [128 * 256];        // layer-1 Wt[n][k] fp16, stacked [Ws|Wn]
__device__ __half g_wt2 [128 * 256];        // layer-2
__device__ int    g_cnt[NN];
__device__ int    g_off[NN + 1];
__device__ int    g_cur[NN];
__device__ int    g_csr[EE];

// ---------------- fused fp32->fp16 convert + cnt zero ----------------
__global__ void cvtzero_kernel(const float4* __restrict__ x4, uint2* __restrict__ xh,
                               int n4, int* __restrict__ cnt) {
    int i = blockIdx.x * blockDim.x + threadIdx.x;
    if (i < NN) cnt[i] = 0;
    if (i >= n4) return;
    float4 v = __ldg(&x4[i]);
    __half2 a = __floats2half2_rn(v.x, v.y);
    __half2 b = __floats2half2_rn(v.z, v.w);
    uint2 o;
    o.x = *(uint32_t*)&a;
    o.y = *(uint32_t*)&b;
    xh[i] = o;
}

// ---------------- CSR build ----------------
__global__ void hist_kernel(const int* __restrict__ dst, int* __restrict__ cnt, int E) {
    int i = (blockIdx.x * blockDim.x + threadIdx.x) * 4;
    if (i + 3 < E) {
        int4 d = __ldg((const int4*)(dst + i));
        atomicAdd(&cnt[d.x], 1);
        atomicAdd(&cnt[d.y], 1);
        atomicAdd(&cnt[d.z], 1);
        atomicAdd(&cnt[d.w], 1);
    } else {
        for (int k = i; k < E; k++) atomicAdd(&cnt[__ldg(&dst[k])], 1);
    }
}

__global__ __launch_bounds__(SCAN_T) void scan_kernel(const int* __restrict__ cnt,
                                                      int* __restrict__ off,
                                                      int* __restrict__ cur) {
    __shared__ int ssum[SCAN_T];
    int t = threadIdx.x;
    int start = t * CHUNK;
    int s = 0;
    for (int i = 0; i < CHUNK; i++) {
        int idx = start + i;
        if (idx < NN) s += cnt[idx];
    }
    ssum[t] = s;
    __syncthreads();
    for (int d = 1; d < SCAN_T; d <<= 1) {
        int v = (t >= d) ? ssum[t - d] : 0;
        __syncthreads();
        ssum[t] += v;
        __syncthreads();
    }
    int running = (t == 0) ? 0 : ssum[t - 1];
    for (int i = 0; i < CHUNK; i++) {
        int idx = start + i;
        if (idx < NN) {
            off[idx] = running;
            cur[idx] = running;
            running += cnt[idx];
        }
    }
    if (t == SCAN_T - 1) off[NN] = running;
}

__global__ void fill_kernel(const int* __restrict__ src, const int* __restrict__ dst,
                            int* __restrict__ cur, int* __restrict__ csr, int E) {
    int i = (blockIdx.x * blockDim.x + threadIdx.x) * 4;
    if (i + 3 < E) {
        int4 d = __ldg((const int4*)(dst + i));
        int4 s = __ldg((const int4*)(src + i));
        csr[atomicAdd(&cur[d.x], 1)] = s.x;
        csr[atomicAdd(&cur[d.y], 1)] = s.y;
        csr[atomicAdd(&cur[d.z], 1)] = s.z;
        csr[atomicAdd(&cur[d.w], 1)] = s.w;
    } else {
        for (int k = i; k < E; k++)
            csr[atomicAdd(&cur[__ldg(&dst[k])], 1)] = __ldg(&src[k]);
    }
}

// ---------------- W pre-transpose: Wt[n][k] = W[k][n], fp16, stacked (both layers) ----------------
__global__ void wprep_kernel(const float* __restrict__ W1s, const float* __restrict__ W1n,
                             const float* __restrict__ W2s, const float* __restrict__ W2n,
                             __half* __restrict__ wt1, __half* __restrict__ wt2) {
    __shared__ float tile[32][33];
    int k0 = blockIdx.x * 32, n0 = blockIdx.y * 32;
    int z  = blockIdx.z;                   // 0=W1s 1=W1n 2=W2s 3=W2n
    const float* W = (z == 0) ? W1s : (z == 1) ? W1n : (z == 2) ? W2s : W2n;
    __half* wt = (z < 2) ? wt1 : wt2;
    int w = z & 1;
    int tx = threadIdx.x, ty = threadIdx.y;   // (32, 8)
    #pragma unroll
    for (int i = ty; i < 32; i += 8)
        tile[i][tx] = __ldg(&W[(k0 + i) * 128 + n0 + tx]);   // coalesced read (n contig)
    __syncthreads();
    #pragma unroll
    for (int i = ty; i < 32; i += 8)
        wt[(n0 + i) * 256 + w * 128 + k0 + tx] =
            __float2half_rn(tile[tx][i]);                     // coalesced write (k contig)
}

// ---------------- mean gather (fp16 rows, fp32 accum, fp16 out): warp per node ----------------
__device__ __forceinline__ void acc_u2(float2& a01, float2& a23, uint2 u) {
    float2 f0 = __half22float2(*(__half2*)&u.x);
    float2 f1 = __half22float2(*(__half2*)&u.y);
    a01.x += f0.x; a01.y += f0.y;
    a23.x += f1.x; a23.y += f1.y;
}

__global__ __launch_bounds__(256) void gather_kernel(
    const uint2* __restrict__ xh,    // [N][32] fp16 rows
    const int* __restrict__ off,     // [N+1]
    const int* __restrict__ csr,     // [E]
    uint2* __restrict__ aggh)        // [N][32] <- mean (fp16)
{
    int gw = (blockIdx.x * blockDim.x + threadIdx.x) >> 5;   // node id
    if (gw >= NN) return;
    int lane = threadIdx.x & 31;
    int beg = __ldg(&off[gw]);
    int end = __ldg(&off[gw + 1]);

    float2 a01 = make_float2(0.f, 0.f);
    float2 a23 = make_float2(0.f, 0.f);
    int j = beg;

    // 16-deep batches first (deg mean ~16 -> usually one MLP-16 burst)
    #pragma unroll 1
    for (; j + 16 <= end; j += 16) {
        int s[16];
        #pragma unroll
        for (int q = 0; q < 16; q++) s[q] = __ldg(&csr[j + q]);
        uint2 u[16];
        #pragma unroll
        for (int q = 0; q < 16; q++) u[q] = __ldg(&xh[(size_t)s[q] * 32 + lane]);
        #pragma unroll
        for (int q = 0; q < 16; q++) acc_u2(a01, a23, u[q]);
    }
    // 8-deep
    #pragma unroll 1
    for (; j + 8 <= end; j += 8) {
        int s[8];
        #pragma unroll
        for (int q = 0; q < 8; q++) s[q] = __ldg(&csr[j + q]);
        uint2 u[8];
        #pragma unroll
        for (int q = 0; q < 8; q++) u[q] = __ldg(&xh[(size_t)s[q] * 32 + lane]);
        #pragma unroll
        for (int q = 0; q < 8; q++) acc_u2(a01, a23, u[q]);
    }
    // scalar tail
    #pragma unroll 1
    for (; j < end; j++) {
        int s = __ldg(&csr[j]);
        uint2 u = __ldg(&xh[(size_t)s * 32 + lane]);
        acc_u2(a01, a23, u);
    }

    float inv = 1.0f / fmaxf((float)(end - beg), 1.0f);
    __half2 h0 = __floats2half2_rn(a01.x * inv, a01.y * inv);
    __half2 h1 = __floats2half2_rn(a23.x * inv, a23.y * inv);
    uint2 o;
    o.x = *(uint32_t*)&h0;
    o.y = *(uint32_t*)&h1;
    aggh[(size_t)gw * 32 + lane] = o;
}

// ======================= fp16 mma.sync GEMM layer =======================
// out[0:N,0:128] = relu?( [x | mean] @ Wt^T + b )   (K = 256, fp16 in, fp32 accum)
// Tile: 128 nodes x 128 cols, 8 warps 4x2 (warp: 32 rows x 64 cols), m16n8k16.

#define MMA_F16(c, a, b)                                                         \
    asm volatile("mma.sync.aligned.m16n8k16.row.col.f32.f16.f16.f32 "            \
                 "{%0,%1,%2,%3}, {%4,%5,%6,%7}, {%8,%9}, {%0,%1,%2,%3};"         \
                 : "+f"((c)[0]), "+f"((c)[1]), "+f"((c)[2]), "+f"((c)[3])        \
                 : "r"((a)[0]), "r"((a)[1]), "r"((a)[2]), "r"((a)[3]),           \
                   "r"((b)[0]), "r"((b)[1]))

#define ASTRIDE_H 136   // halves per A row (68 words, 68%32==4 -> conflict-free frags)
#define BSTRIDE_H 264   // halves per B row (132 words, 132%32==4), k=0..255
#define BIAS_BYTES 512
#define AS_BYTES  (128 * ASTRIDE_H * 2)               // 34816
#define BS_OFF_B  (BIAS_BYTES + AS_BYTES)             // 35328
#define SM_BYTES  (BS_OFF_B + 128 * BSTRIDE_H * 2)    // 102912

__global__ __launch_bounds__(256, 2) void layer_mma_kernel(
    const uint2* __restrict__ selfh, // [N][32] fp16 self features
    const uint2* __restrict__ aggh,  // [N][32] fp16 neighbor mean
    const __half* __restrict__ wt,   // [128 n][256 k] fp16 pre-transposed stacked W
    const float* __restrict__ bias,  // [128] fp32
    float* __restrict__ out_f,       // [N,128] fp32 (or nullptr)
    __half* __restrict__ out_h,      // [N,128] fp16 (or nullptr)
    int do_relu)
{
    extern __shared__ char smem[];
    float*  bsm = (float*)smem;                       // [128]
    __half* As  = (__half*)(smem + BIAS_BYTES);       // [128][ASTRIDE_H]
    __half* Bs  = (__half*)(smem + BS_OFF_B);         // [128 n][BSTRIDE_H]
    const int tid = threadIdx.x;
    const int wid = tid >> 5, lane = tid & 31;
    const int g = lane >> 2, tg = lane & 3;
    const int warp_m = wid & 3, warp_n = wid >> 2;
    const int base = blockIdx.x * 128;

    if (tid < 128) bsm[tid] = __ldg(&bias[tid]);

    // ---- stage B: straight uint4 copy of Wt (coalesced LDG, conflict-free STS) ----
    {
        const uint4* wt4 = (const uint4*)wt;          // 4096 uint4 (8 halves each)
        #pragma unroll
        for (int idx = tid; idx < 4096; idx += 256) {
            int n = idx >> 5, kq = idx & 31;          // kq: 8-half chunk along k
            *(uint4*)&Bs[n * BSTRIDE_H + kq * 8] = __ldg(&wt4[idx]);
        }
    }

    float c[2][8][4];
    #pragma unroll
    for (int mt = 0; mt < 2; mt++)
        #pragma unroll
        for (int nt = 0; nt < 8; nt++)
            #pragma unroll
            for (int q = 0; q < 4; q++) c[mt][nt][q] = 0.f;

    // ---- two K-passes: pass0 = self (k 0..127), pass1 = mean (k 128..255) ----
    #pragma unroll 1
    for (int pass = 0; pass < 2; pass++) {
        const uint4* srcA = (const uint4*)(pass ? aggh : selfh);  // 16B = 8 halves
        __syncthreads();   // previous-pass readers done before As overwrite
        #pragma unroll 8
        for (int idx = tid; idx < 2048; idx += 256) {     // 128 rows x 16 uint4
            int r = idx >> 4, q = idx & 15;
            int node = base + r;
            uint4 v = make_uint4(0u, 0u, 0u, 0u);
            if (node < NN) v = __ldg(&srcA[(size_t)node * 16 + q]);
            *(uint4*)&As[r * ASTRIDE_H + q * 8] = v;
        }
        __syncthreads();

        const __half* arow = &As[(warp_m * 32 + g) * ASTRIDE_H + 2 * tg];
        const __half* brow = &Bs[(warp_n * 64 + g) * BSTRIDE_H + 2 * tg + pass * 128];

        #pragma unroll
        for (int ks = 0; ks < 8; ks++) {                  // K = 128 per pass, k16 steps
            const int kb = ks * 16;
            uint32_t a[2][4];
            #pragma unroll
            for (int mt = 0; mt < 2; mt++) {
                const __half* p = arow + mt * 16 * ASTRIDE_H + kb;
                a[mt][0] = *(const uint32_t*)(p);
                a[mt][1] = *(const uint32_t*)(p + 8 * ASTRIDE_H);
                a[mt][2] = *(const uint32_t*)(p + 8);
                a[mt][3] = *(const uint32_t*)(p + 8 * ASTRIDE_H + 8);
            }
            uint32_t b[8][2];
            #pragma unroll
            for (int nt = 0; nt < 8; nt++) {
                const __half* p = brow + nt * 8 * BSTRIDE_H + kb;
                b[nt][0] = *(const uint32_t*)(p);
                b[nt][1] = *(const uint32_t*)(p + 8);
            }
            #pragma unroll
            for (int mt = 0; mt < 2; mt++)
                #pragma unroll
                for (int nt = 0; nt < 8; nt++)
                    MMA_F16(c[mt][nt], a[mt], b[nt]);
        }
    }

    // ---- epilogue: bias (+relu), fp32 and/or fp16 stores ----
    #pragma unroll
    for (int mt = 0; mt < 2; mt++) {
        #pragma unroll
        for (int half = 0; half < 2; half++) {
            int row = warp_m * 32 + mt * 16 + half * 8 + g;
            int node = base + row;
            if (node < NN) {
                #pragma unroll
                for (int nt = 0; nt < 8; nt++) {
                    int col = warp_n * 64 + nt * 8 + tg * 2;
                    float v0 = c[mt][nt][half * 2 + 0] + bsm[col];
                    float v1 = c[mt][nt][half * 2 + 1] + bsm[col + 1];
                    if (do_relu) { v0 = fmaxf(v0, 0.f); v1 = fmaxf(v1, 0.f); }
                    if (out_f)
                        *(float2*)(out_f + (size_t)node * 128 + col) = make_float2(v0, v1);
                    if (out_h) {
                        __half2 h = __floats2half2_rn(v0, v1);
                        *(__half2*)(out_h + (size_t)node * 128 + col) = h;
                    }
                }
            }
        }
    }
}

// ---------------- launch ----------------
extern "C" void kernel_launch(void* const* d_in, const int* in_sizes, int n_in,
                              void* d_out, int out_size) {
    const float* in_feat  = (const float*)d_in[0];
    const float* W1_self  = (const float*)d_in[1];
    const float* W1_neigh = (const float*)d_in[2];
    const float* b1       = (const float*)d_in[3];
    const float* W2_self  = (const float*)d_in[4];
    const float* W2_neigh = (const float*)d_in[5];
    const float* b2       = (const float*)d_in[6];
    const int*   src      = (const int*)d_in[7];
    const int*   dst      = (const int*)d_in[8];
    const int E = in_sizes[7];

    float* out = (float*)d_out;

    uint2 *xh, *h1h, *aggh;
    __half *wt1, *wt2;
    int *cnt, *off, *cur, *csr;
    cudaGetSymbolAddress((void**)&xh,   g_xh);
    cudaGetSymbolAddress((void**)&h1h,  g_h1h);
    cudaGetSymbolAddress((void**)&aggh, g_aggh);
    cudaGetSymbolAddress((void**)&wt1,  g_wt1);
    cudaGetSymbolAddress((void**)&wt2,  g_wt2);
    cudaGetSymbolAddress((void**)&cnt,  g_cnt);
    cudaGetSymbolAddress((void**)&off,  g_off);
    cudaGetSymbolAddress((void**)&cur,  g_cur);
    cudaGetSymbolAddress((void**)&csr,  g_csr);

    cudaFuncSetAttribute(layer_mma_kernel, cudaFuncAttributeMaxDynamicSharedMemorySize, SM_BYTES);

    const int cb  = (NN * 32 + 255) / 256;        // cvt grid (covers NN too)
    const int eb4 = (E / 4 + 255) / 256;          // 4 edges per thread
    const int gb  = (NN * 32 + 255) / 256;        // warp per node
    const int lb  = (NN + 127) / 128;             // 128-node tiles
    dim3 wgrid(4, 4, 4), wblk(32, 8);

    // ---- prep + CSR build ----
    cvtzero_kernel<<<cb, 256>>>((const float4*)in_feat, xh, NN * 32, cnt);
    hist_kernel<<<eb4, 256>>>(dst, cnt, E);
    scan_kernel<<<1, SCAN_T>>>(cnt, off, cur);
    fill_kernel<<<eb4, 256>>>(src, dst, cur, csr, E);
    wprep_kernel<<<wgrid, wblk>>>(W1_self, W1_neigh, W2_self, W2_neigh, wt1, wt2);

    // ---- layer 1 ----
    gather_kernel<<<gb, 256>>>(xh, off, csr, aggh);
    layer_mma_kernel<<<lb, 256, SM_BYTES>>>(xh, aggh, wt1, b1,
                                            nullptr, (__half*)h1h, 1);

    // ---- layer 2 ----
    gather_kernel<<<gb, 256>>>(h1h, off, csr, aggh);
    layer_mma_kernel<<<lb, 256, SM_BYTES>>>(h1h, aggh, wt2, b2,
                                            out, nullptr, 0);
}

// round 14
// speedup vs baseline: 1.0919x; 1.0146x over previous
#include <cuda_runtime.h>
#include <cuda_fp16.h>
#include <cstdint>

#define NN 100000
#define EE 1600000
#define DD 128
#define SCAN_T 1024
#define CHUNK  98      // ceil(NN / SCAN_T)
#define CVT_BLOCKS 12500   // NN*32/256

// ---------------- scratch (no allocations allowed) ----------------
__device__ uint2  g_xh  [(size_t)NN * 32];  // fp16 in_feat / layer-1 input
__device__ uint2  g_h1h [(size_t)NN * 32];  // fp16 h1
__device__ uint2  g_aggh[(size_t)NN * 32];  // fp16 neighbor mean
__device__ __half g_wt1 [128 * 256];        // layer-1 Wt[n][k] fp16, stacked [Ws|Wn]
__device__ __half g_wt2 [128 * 256];        // layer-2
__device__ int    g_cnt[NN];                // zero at load; re-zeroed in fill each call
__device__ int    g_off[NN + 1];
__device__ int    g_cur[NN];
__device__ int    g_csr[EE];

// ---------------- fused prep: cvt (fp32->fp16) + hist + wprep ----------------
__global__ void prep_kernel(const float4* __restrict__ x4, uint2* __restrict__ xh,
                            const int* __restrict__ dst, int* __restrict__ cnt,
                            const float* __restrict__ W1s, const float* __restrict__ W1n,
                            const float* __restrict__ W2s, const float* __restrict__ W2n,
                            __half* __restrict__ wt1, __half* __restrict__ wt2,
                            int E, int eb4) {
    const int bid = blockIdx.x;
    const int t = threadIdx.x;
    if (bid < CVT_BLOCKS) {
        // ---- fp32 -> fp16 convert ----
        int i = bid * 256 + t;                 // < NN*32
        float4 v = __ldg(&x4[i]);
        __half2 a = __floats2half2_rn(v.x, v.y);
        __half2 b = __floats2half2_rn(v.z, v.w);
        uint2 o;
        o.x = *(uint32_t*)&a;
        o.y = *(uint32_t*)&b;
        xh[i] = o;
    } else if (bid < CVT_BLOCKS + eb4) {
        // ---- degree histogram (4 edges / thread) ----
        int i = ((bid - CVT_BLOCKS) * 256 + t) * 4;
        if (i + 3 < E) {
            int4 d = __ldg((const int4*)(dst + i));
            atomicAdd(&cnt[d.x], 1);
            atomicAdd(&cnt[d.y], 1);
            atomicAdd(&cnt[d.z], 1);
            atomicAdd(&cnt[d.w], 1);
        } else {
            for (int k = i; k < E; k++) atomicAdd(&cnt[__ldg(&dst[k])], 1);
        }
    } else {
        // ---- W pre-transpose: Wt[n][k] = W[k][n], fp16, stacked ----
        __shared__ float tile[32][33];
        int b = bid - CVT_BLOCKS - eb4;        // 0..63
        int z = b >> 4;                        // 0=W1s 1=W1n 2=W2s 3=W2n
        int rem = b & 15;
        int k0 = (rem >> 2) * 32, n0 = (rem & 3) * 32;
        const float* W = (z == 0) ? W1s : (z == 1) ? W1n : (z == 2) ? W2s : W2n;
        __half* wt = (z < 2) ? wt1 : wt2;
        int w = z & 1;
        int tx = t & 31, ty = t >> 5;          // (32, 8)
        #pragma unroll
        for (int i = ty; i < 32; i += 8)
            tile[i][tx] = __ldg(&W[(k0 + i) * 128 + n0 + tx]);
        __syncthreads();
        #pragma unroll
        for (int i = ty; i < 32; i += 8)
            wt[(n0 + i) * 256 + w * 128 + k0 + tx] = __float2half_rn(tile[tx][i]);
    }
}

// ---------------- scan ----------------
__global__ __launch_bounds__(SCAN_T) void scan_kernel(const int* __restrict__ cnt,
                                                      int* __restrict__ off,
                                                      int* __restrict__ cur) {
    __shared__ int ssum[SCAN_T];
    int t = threadIdx.x;
    int start = t * CHUNK;
    int s = 0;
    for (int i = 0; i < CHUNK; i++) {
        int idx = start + i;
        if (idx < NN) s += cnt[idx];
    }
    ssum[t] = s;
    __syncthreads();
    for (int d = 1; d < SCAN_T; d <<= 1) {
        int v = (t >= d) ? ssum[t - d] : 0;
        __syncthreads();
        ssum[t] += v;
        __syncthreads();
    }
    int running = (t == 0) ? 0 : ssum[t - 1];
    for (int i = 0; i < CHUNK; i++) {
        int idx = start + i;
        if (idx < NN) {
            off[idx] = running;
            cur[idx] = running;
            running += cnt[idx];
        }
    }
    if (t == SCAN_T - 1) off[NN] = running;
}

// ---------------- fill (+ cnt re-zero for next call; cnt dead after scan) ----------------
__global__ void fill_kernel(const int* __restrict__ src, const int* __restrict__ dst,
                            int* __restrict__ cur, int* __restrict__ csr,
                            int* __restrict__ cnt, int E) {
    int gid = blockIdx.x * blockDim.x + threadIdx.x;
    for (int i = gid; i < NN; i += gridDim.x * blockDim.x) cnt[i] = 0;
    int i = gid * 4;
    if (i + 3 < E) {
        int4 d = __ldg((const int4*)(dst + i));
        int4 s = __ldg((const int4*)(src + i));
        csr[atomicAdd(&cur[d.x], 1)] = s.x;
        csr[atomicAdd(&cur[d.y], 1)] = s.y;
        csr[atomicAdd(&cur[d.z], 1)] = s.z;
        csr[atomicAdd(&cur[d.w], 1)] = s.w;
    } else {
        for (int k = i; k < E; k++)
            csr[atomicAdd(&cur[__ldg(&dst[k])], 1)] = __ldg(&src[k]);
    }
}

// ---------------- mean gather (fp16 rows, fp32 accum, fp16 out): warp per node ----------------
__device__ __forceinline__ void acc_u2(float2& a01, float2& a23, uint2 u) {
    float2 f0 = __half22float2(*(__half2*)&u.x);
    float2 f1 = __half22float2(*(__half2*)&u.y);
    a01.x += f0.x; a01.y += f0.y;
    a23.x += f1.x; a23.y += f1.y;
}

__global__ __launch_bounds__(256) void gather_kernel(
    const uint2* __restrict__ xh,    // [N][32] fp16 rows
    const int* __restrict__ off,     // [N+1]
    const int* __restrict__ csr,     // [E]
    uint2* __restrict__ aggh)        // [N][32] <- mean (fp16)
{
    int gw = (blockIdx.x * blockDim.x + threadIdx.x) >> 5;   // node id
    if (gw >= NN) return;
    int lane = threadIdx.x & 31;
    int beg = __ldg(&off[gw]);
    int end = __ldg(&off[gw + 1]);

    float2 a01 = make_float2(0.f, 0.f);
    float2 a23 = make_float2(0.f, 0.f);
    int j = beg;

    // 16-deep batches first (deg mean ~16 -> usually one MLP-16 burst)
    #pragma unroll 1
    for (; j + 16 <= end; j += 16) {
        int s[16];
        #pragma unroll
        for (int q = 0; q < 16; q++) s[q] = __ldg(&csr[j + q]);
        uint2 u[16];
        #pragma unroll
        for (int q = 0; q < 16; q++) u[q] = __ldg(&xh[(size_t)s[q] * 32 + lane]);
        #pragma unroll
        for (int q = 0; q < 16; q++) acc_u2(a01, a23, u[q]);
    }
    // 8-deep
    #pragma unroll 1
    for (; j + 8 <= end; j += 8) {
        int s[8];
        #pragma unroll
        for (int q = 0; q < 8; q++) s[q] = __ldg(&csr[j + q]);
        uint2 u[8];
        #pragma unroll
        for (int q = 0; q < 8; q++) u[q] = __ldg(&xh[(size_t)s[q] * 32 + lane]);
        #pragma unroll
        for (int q = 0; q < 8; q++) acc_u2(a01, a23, u[q]);
    }
    // scalar tail
    #pragma unroll 1
    for (; j < end; j++) {
        int s = __ldg(&csr[j]);
        uint2 u = __ldg(&xh[(size_t)s * 32 + lane]);
        acc_u2(a01, a23, u);
    }

    float inv = 1.0f / fmaxf((float)(end - beg), 1.0f);
    __half2 h0 = __floats2half2_rn(a01.x * inv, a01.y * inv);
    __half2 h1 = __floats2half2_rn(a23.x * inv, a23.y * inv);
    uint2 o;
    o.x = *(uint32_t*)&h0;
    o.y = *(uint32_t*)&h1;
    aggh[(size_t)gw * 32 + lane] = o;
}

// ======================= fp16 mma.sync GEMM layer =======================
// out[0:N,0:128] = relu?( [x | mean] @ Wt^T + b )   (K = 256, fp16 in, fp32 accum)
// Tile: 128 nodes x 128 cols, 8 warps 4x2 (warp: 32 rows x 64 cols), m16n8k16.

#define MMA_F16(c, a, b)                                                         \
    asm volatile("mma.sync.aligned.m16n8k16.row.col.f32.f16.f16.f32 "            \
                 "{%0,%1,%2,%3}, {%4,%5,%6,%7}, {%8,%9}, {%0,%1,%2,%3};"         \
                 : "+f"((c)[0]), "+f"((c)[1]), "+f"((c)[2]), "+f"((c)[3])        \
                 : "r"((a)[0]), "r"((a)[1]), "r"((a)[2]), "r"((a)[3]),           \
                   "r"((b)[0]), "r"((b)[1]))

#define ASTRIDE_H 136   // halves per A row (68 words, 68%32==4 -> conflict-free frags)
#define BSTRIDE_H 264   // halves per B row (132 words, 132%32==4), k=0..255
#define BIAS_BYTES 512
#define AS_BYTES  (128 * ASTRIDE_H * 2)               // 34816
#define BS_OFF_B  (BIAS_BYTES + AS_BYTES)             // 35328
#define SM_BYTES  (BS_OFF_B + 128 * BSTRIDE_H * 2)    // 102912

__global__ __launch_bounds__(256, 2) void layer_mma_kernel(
    const uint2* __restrict__ selfh, // [N][32] fp16 self features
    const uint2* __restrict__ aggh,  // [N][32] fp16 neighbor mean
    const __half* __restrict__ wt,   // [128 n][256 k] fp16 pre-transposed stacked W
    const float* __restrict__ bias,  // [128] fp32
    float* __restrict__ out_f,       // [N,128] fp32 (or nullptr)
    __half* __restrict__ out_h,      // [N,128] fp16 (or nullptr)
    int do_relu)
{
    extern __shared__ char smem[];
    float*  bsm = (float*)smem;                       // [128]
    __half* As  = (__half*)(smem + BIAS_BYTES);       // [128][ASTRIDE_H]
    __half* Bs  = (__half*)(smem + BS_OFF_B);         // [128 n][BSTRIDE_H]
    const int tid = threadIdx.x;
    const int wid = tid >> 5, lane = tid & 31;
    const int g = lane >> 2, tg = lane & 3;
    const int warp_m = wid & 3, warp_n = wid >> 2;
    const int base = blockIdx.x * 128;

    if (tid < 128) bsm[tid] = __ldg(&bias[tid]);

    // ---- stage B: straight uint4 copy of Wt (coalesced LDG, conflict-free STS) ----
    {
        const uint4* wt4 = (const uint4*)wt;          // 4096 uint4 (8 halves each)
        #pragma unroll
        for (int idx = tid; idx < 4096; idx += 256) {
            int n = idx >> 5, kq = idx & 31;          // kq: 8-half chunk along k
            *(uint4*)&Bs[n * BSTRIDE_H + kq * 8] = __ldg(&wt4[idx]);
        }
    }

    float c[2][8][4];
    #pragma unroll
    for (int mt = 0; mt < 2; mt++)
        #pragma unroll
        for (int nt = 0; nt < 8; nt++)
            #pragma unroll
            for (int q = 0; q < 4; q++) c[mt][nt][q] = 0.f;

    // ---- two K-passes: pass0 = self (k 0..127), pass1 = mean (k 128..255) ----
    #pragma unroll 1
    for (int pass = 0; pass < 2; pass++) {
        const uint4* srcA = (const uint4*)(pass ? aggh : selfh);  // 16B = 8 halves
        __syncthreads();   // previous-pass readers done before As overwrite
        #pragma unroll 8
        for (int idx = tid; idx < 2048; idx += 256) {     // 128 rows x 16 uint4
            int r = idx >> 4, q = idx & 15;
            int node = base + r;
            uint4 v = make_uint4(0u, 0u, 0u, 0u);
            if (node < NN) v = __ldg(&srcA[(size_t)node * 16 + q]);
            *(uint4*)&As[r * ASTRIDE_H + q * 8] = v;
        }
        __syncthreads();

        const __half* arow = &As[(warp_m * 32 + g) * ASTRIDE_H + 2 * tg];
        const __half* brow = &Bs[(warp_n * 64 + g) * BSTRIDE_H + 2 * tg + pass * 128];

        #pragma unroll
        for (int ks = 0; ks < 8; ks++) {                  // K = 128 per pass, k16 steps
            const int kb = ks * 16;
            uint32_t a[2][4];
            #pragma unroll
            for (int mt = 0; mt < 2; mt++) {
                const __half* p = arow + mt * 16 * ASTRIDE_H + kb;
                a[mt][0] = *(const uint32_t*)(p);
                a[mt][1] = *(const uint32_t*)(p + 8 * ASTRIDE_H);
                a[mt][2] = *(const uint32_t*)(p + 8);
                a[mt][3] = *(const uint32_t*)(p + 8 * ASTRIDE_H + 8);
            }
            uint32_t b[8][2];
            #pragma unroll
            for (int nt = 0; nt < 8; nt++) {
                const __half* p = brow + nt * 8 * BSTRIDE_H + kb;
                b[nt][0] = *(const uint32_t*)(p);
                b[nt][1] = *(const uint32_t*)(p + 8);
            }
            #pragma unroll
            for (int mt = 0; mt < 2; mt++)
                #pragma unroll
                for (int nt = 0; nt < 8; nt++)
                    MMA_F16(c[mt][nt], a[mt], b[nt]);
        }
    }

    // ---- epilogue: bias (+relu), fp32 and/or fp16 stores ----
    #pragma unroll
    for (int mt = 0; mt < 2; mt++) {
        #pragma unroll
        for (int half = 0; half < 2; half++) {
            int row = warp_m * 32 + mt * 16 + half * 8 + g;
            int node = base + row;
            if (node < NN) {
                #pragma unroll
                for (int nt = 0; nt < 8; nt++) {
                    int col = warp_n * 64 + nt * 8 + tg * 2;
                    float v0 = c[mt][nt][half * 2 + 0] + bsm[col];
                    float v1 = c[mt][nt][half * 2 + 1] + bsm[col + 1];
                    if (do_relu) { v0 = fmaxf(v0, 0.f); v1 = fmaxf(v1, 0.f); }
                    if (out_f)
                        *(float2*)(out_f + (size_t)node * 128 + col) = make_float2(v0, v1);
                    if (out_h) {
                        __half2 h = __floats2half2_rn(v0, v1);
                        *(__half2*)(out_h + (size_t)node * 128 + col) = h;
                    }
                }
            }
        }
    }
}

// ---------------- launch ----------------
extern "C" void kernel_launch(void* const* d_in, const int* in_sizes, int n_in,
                              void* d_out, int out_size) {
    const float* in_feat  = (const float*)d_in[0];
    const float* W1_self  = (const float*)d_in[1];
    const float* W1_neigh = (const float*)d_in[2];
    const float* b1       = (const float*)d_in[3];
    const float* W2_self  = (const float*)d_in[4];
    const float* W2_neigh = (const float*)d_in[5];
    const float* b2       = (const float*)d_in[6];
    const int*   src      = (const int*)d_in[7];
    const int*   dst      = (const int*)d_in[8];
    const int E = in_sizes[7];

    float* out = (float*)d_out;

    uint2 *xh, *h1h, *aggh;
    __half *wt1, *wt2;
    int *cnt, *off, *cur, *csr;
    cudaGetSymbolAddress((void**)&xh,   g_xh);
    cudaGetSymbolAddress((void**)&h1h,  g_h1h);
    cudaGetSymbolAddress((void**)&aggh, g_aggh);
    cudaGetSymbolAddress((void**)&wt1,  g_wt1);
    cudaGetSymbolAddress((void**)&wt2,  g_wt2);
    cudaGetSymbolAddress((void**)&cnt,  g_cnt);
    cudaGetSymbolAddress((void**)&off,  g_off);
    cudaGetSymbolAddress((void**)&cur,  g_cur);
    cudaGetSymbolAddress((void**)&csr,  g_csr);

    cudaFuncSetAttribute(layer_mma_kernel, cudaFuncAttributeMaxDynamicSharedMemorySize, SM_BYTES);

    const int eb4 = (E / 4 + 255) / 256;          // hist/fill blocks (4 edges/thread)
    const int pb  = CVT_BLOCKS + eb4 + 64;        // fused prep grid
    const int gb  = (NN * 32 + 255) / 256;        // warp per node
    const int lb  = (NN + 127) / 128;             // 128-node tiles

    // 1: fused prep (cvt + hist + wprep)   [cnt is zero: load-init / re-zeroed in fill]
    prep_kernel<<<pb, 256>>>((const float4*)in_feat, xh, dst, cnt,
                             W1_self, W1_neigh, W2_self, W2_neigh, wt1, wt2, E, eb4);
    // 2: scan
    scan_kernel<<<1, SCAN_T>>>(cnt, off, cur);
    // 3: fill (+ cnt re-zero for next call)
    fill_kernel<<<eb4, 256>>>(src, dst, cur, csr, cnt, E);
    // 4: gather layer 1  <-- profiled launch
    gather_kernel<<<gb, 256>>>(xh, off, csr, aggh);
    // 5: layer 1
    layer_mma_kernel<<<lb, 256, SM_BYTES>>>(xh, aggh, wt1, b1,
                                            nullptr, (__half*)h1h, 1);
    // 6: gather layer 2
    gather_kernel<<<gb, 256>>>(h1h, off, csr, aggh);
    // 7: layer 2
    layer_mma_kernel<<<lb, 256, SM_BYTES>>>(h1h, aggh, wt2, b2,
                                            out, nullptr, 0);
}

// round 15
// speedup vs baseline: 1.1153x; 1.0214x over previous
#include <cuda_runtime.h>
#include <cuda_fp16.h>
#include <cstdint>

#define NN 100000
#define EE 1600000
#define DD 128
#define SCAN_T 1024
#define CHUNK  98      // ceil(NN / SCAN_T)
#define CVT_BLOCKS 12500   // NN*32/256

// ---------------- scratch (no allocations allowed) ----------------
__device__ uint2  g_xh  [(size_t)NN * 32];  // fp16 in_feat / layer-1 input
__device__ uint2  g_h1h [(size_t)NN * 32];  // fp16 h1
__device__ uint2  g_aggh[(size_t)NN * 32];  // fp16 neighbor mean
__device__ __half g_wt1 [128 * 256];        // layer-1 Wt[n][k] fp16, stacked [Ws|Wn]
__device__ __half g_wt2 [128 * 256];        // layer-2
__device__ int    g_cnt[NN];                // zero at load; re-zeroed in fill each call
__device__ int    g_off[NN + 1];
__device__ int    g_cur[NN];
__device__ int    g_csrb[EE];               // byte offsets: src*256

// ---------------- fused prep: cvt (fp32->fp16) + hist + wprep ----------------
__global__ void prep_kernel(const float4* __restrict__ x4, uint2* __restrict__ xh,
                            const int* __restrict__ dst, int* __restrict__ cnt,
                            const float* __restrict__ W1s, const float* __restrict__ W1n,
                            const float* __restrict__ W2s, const float* __restrict__ W2n,
                            __half* __restrict__ wt1, __half* __restrict__ wt2,
                            int E, int eb4) {
    const int bid = blockIdx.x;
    const int t = threadIdx.x;
    if (bid < CVT_BLOCKS) {
        // ---- fp32 -> fp16 convert ----
        int i = bid * 256 + t;                 // < NN*32
        float4 v = __ldg(&x4[i]);
        __half2 a = __floats2half2_rn(v.x, v.y);
        __half2 b = __floats2half2_rn(v.z, v.w);
        uint2 o;
        o.x = *(uint32_t*)&a;
        o.y = *(uint32_t*)&b;
        xh[i] = o;
    } else if (bid < CVT_BLOCKS + eb4) {
        // ---- degree histogram (4 edges / thread) ----
        int i = ((bid - CVT_BLOCKS) * 256 + t) * 4;
        if (i + 3 < E) {
            int4 d = __ldg((const int4*)(dst + i));
            atomicAdd(&cnt[d.x], 1);
            atomicAdd(&cnt[d.y], 1);
            atomicAdd(&cnt[d.z], 1);
            atomicAdd(&cnt[d.w], 1);
        } else {
            for (int k = i; k < E; k++) atomicAdd(&cnt[__ldg(&dst[k])], 1);
        }
    } else {
        // ---- W pre-transpose: Wt[n][k] = W[k][n], fp16, stacked ----
        __shared__ float tile[32][33];
        int b = bid - CVT_BLOCKS - eb4;        // 0..63
        int z = b >> 4;                        // 0=W1s 1=W1n 2=W2s 3=W2n
        int rem = b & 15;
        int k0 = (rem >> 2) * 32, n0 = (rem & 3) * 32;
        const float* W = (z == 0) ? W1s : (z == 1) ? W1n : (z == 2) ? W2s : W2n;
        __half* wt = (z < 2) ? wt1 : wt2;
        int w = z & 1;
        int tx = t & 31, ty = t >> 5;          // (32, 8)
        #pragma unroll
        for (int i = ty; i < 32; i += 8)
            tile[i][tx] = __ldg(&W[(k0 + i) * 128 + n0 + tx]);
        __syncthreads();
        #pragma unroll
        for (int i = ty; i < 32; i += 8)
            wt[(n0 + i) * 256 + w * 128 + k0 + tx] = __float2half_rn(tile[tx][i]);
    }
}

// ---------------- scan ----------------
__global__ __launch_bounds__(SCAN_T) void scan_kernel(const int* __restrict__ cnt,
                                                      int* __restrict__ off,
                                                      int* __restrict__ cur) {
    __shared__ int ssum[SCAN_T];
    int t = threadIdx.x;
    int start = t * CHUNK;
    int s = 0;
    for (int i = 0; i < CHUNK; i++) {
        int idx = start + i;
        if (idx < NN) s += cnt[idx];
    }
    ssum[t] = s;
    __syncthreads();
    for (int d = 1; d < SCAN_T; d <<= 1) {
        int v = (t >= d) ? ssum[t - d] : 0;
        __syncthreads();
        ssum[t] += v;
        __syncthreads();
    }
    int running = (t == 0) ? 0 : ssum[t - 1];
    for (int i = 0; i < CHUNK; i++) {
        int idx = start + i;
        if (idx < NN) {
            off[idx] = running;
            cur[idx] = running;
            running += cnt[idx];
        }
    }
    if (t == SCAN_T - 1) off[NN] = running;
}

// ---------------- fill (csr as byte offsets; + cnt re-zero for next call) ----------------
__global__ void fill_kernel(const int* __restrict__ src, const int* __restrict__ dst,
                            int* __restrict__ cur, int* __restrict__ csrb,
                            int* __restrict__ cnt, int E) {
    int gid = blockIdx.x * blockDim.x + threadIdx.x;
    for (int i = gid; i < NN; i += gridDim.x * blockDim.x) cnt[i] = 0;
    int i = gid * 4;
    if (i + 3 < E) {
        int4 d = __ldg((const int4*)(dst + i));
        int4 s = __ldg((const int4*)(src + i));
        csrb[atomicAdd(&cur[d.x], 1)] = s.x << 8;   // src * 256 bytes/row
        csrb[atomicAdd(&cur[d.y], 1)] = s.y << 8;
        csrb[atomicAdd(&cur[d.z], 1)] = s.z << 8;
        csrb[atomicAdd(&cur[d.w], 1)] = s.w << 8;
    } else {
        for (int k = i; k < E; k++)
            csrb[atomicAdd(&cur[__ldg(&dst[k])], 1)] = __ldg(&src[k]) << 8;
    }
}

// ---------------- mean gather: uint4 lanes, 2 edges/warp-step, fp32 accum ----------------
__device__ __forceinline__ void acc_u4(float* acc, uint4 u) {
    const __half2* h2 = (const __half2*)&u;
    #pragma unroll
    for (int q = 0; q < 4; q++) {
        float2 f = __half22float2(h2[q]);
        acc[2 * q]     += f.x;
        acc[2 * q + 1] += f.y;
    }
}

__global__ __launch_bounds__(256) void gather_kernel(
    const char* __restrict__ xh,     // [N][256B] fp16 rows
    const int* __restrict__ off,     // [N+1]
    const int* __restrict__ csrb,    // [E] byte offsets
    uint4* __restrict__ aggh)        // [N][16] <- mean (fp16)
{
    int gw = (blockIdx.x * blockDim.x + threadIdx.x) >> 5;   // node id
    if (gw >= NN) return;
    const int lane = threadIdx.x & 31;
    const int half = lane >> 4;      // which edge of each pair
    const int sub  = lane & 15;      // 16B chunk within the row
    const char* xbase = xh + sub * 16;
    int beg = __ldg(&off[gw]);
    int end = __ldg(&off[gw + 1]);

    float acc[8];
    #pragma unroll
    for (int q = 0; q < 8; q++) acc[q] = 0.f;

    int j = beg;
    // 16 edges per iteration (8 loads/lane, MLP 8)
    #pragma unroll 1
    for (; j + 16 <= end; j += 16) {
        uint4 u[8];
        #pragma unroll
        for (int i = 0; i < 8; i++) {
            int o = __ldg(&csrb[j + 2 * i + half]);
            u[i] = __ldg((const uint4*)(xbase + (unsigned)o));
        }
        #pragma unroll
        for (int i = 0; i < 8; i++) acc_u4(acc, u[i]);
    }
    // 4 edges per iteration (2 loads/lane)
    #pragma unroll 1
    for (; j + 4 <= end; j += 4) {
        int o0 = __ldg(&csrb[j + half]);
        int o1 = __ldg(&csrb[j + 2 + half]);
        uint4 u0 = __ldg((const uint4*)(xbase + (unsigned)o0));
        uint4 u1 = __ldg((const uint4*)(xbase + (unsigned)o1));
        acc_u4(acc, u0);
        acc_u4(acc, u1);
    }
    // tail: pairs, last odd edge handled by half 0 only
    #pragma unroll 1
    for (; j < end; j += 2) {
        int e = j + half;
        if (e < end) {
            int o = __ldg(&csrb[e]);
            uint4 u = __ldg((const uint4*)(xbase + (unsigned)o));
            acc_u4(acc, u);
        }
    }

    // merge the two half-warps (even/odd edges)
    #pragma unroll
    for (int q = 0; q < 8; q++)
        acc[q] += __shfl_xor_sync(0xffffffffu, acc[q], 16);

    float inv = 1.0f / fmaxf((float)(end - beg), 1.0f);
    if (half == 0) {
        __half2 h[4];
        #pragma unroll
        for (int q = 0; q < 4; q++)
            h[q] = __floats2half2_rn(acc[2 * q] * inv, acc[2 * q + 1] * inv);
        aggh[(size_t)gw * 16 + sub] = *(uint4*)h;
    }
}

// ======================= fp16 mma.sync GEMM layer =======================
// out[0:N,0:128] = relu?( [x | mean] @ Wt^T + b )   (K = 256, fp16 in, fp32 accum)
// Tile: 128 nodes x 128 cols, 8 warps 4x2 (warp: 32 rows x 64 cols), m16n8k16.

#define MMA_F16(c, a, b)                                                         \
    asm volatile("mma.sync.aligned.m16n8k16.row.col.f32.f16.f16.f32 "            \
                 "{%0,%1,%2,%3}, {%4,%5,%6,%7}, {%8,%9}, {%0,%1,%2,%3};"         \
                 : "+f"((c)[0]), "+f"((c)[1]), "+f"((c)[2]), "+f"((c)[3])        \
                 : "r"((a)[0]), "r"((a)[1]), "r"((a)[2]), "r"((a)[3]),           \
                   "r"((b)[0]), "r"((b)[1]))

#define ASTRIDE_H 136   // halves per A row (68 words, 68%32==4 -> conflict-free frags)
#define BSTRIDE_H 264   // halves per B row (132 words, 132%32==4), k=0..255
#define BIAS_BYTES 512
#define AS_BYTES  (128 * ASTRIDE_H * 2)               // 34816
#define BS_OFF_B  (BIAS_BYTES + AS_BYTES)             // 35328
#define SM_BYTES  (BS_OFF_B + 128 * BSTRIDE_H * 2)    // 102912

__global__ __launch_bounds__(256, 2) void layer_mma_kernel(
    const uint2* __restrict__ selfh, // [N][32] fp16 self features
    const uint2* __restrict__ aggh,  // [N][32] fp16 neighbor mean
    const __half* __restrict__ wt,   // [128 n][256 k] fp16 pre-transposed stacked W
    const float* __restrict__ bias,  // [128] fp32
    float* __restrict__ out_f,       // [N,128] fp32 (or nullptr)
    __half* __restrict__ out_h,      // [N,128] fp16 (or nullptr)
    int do_relu)
{
    extern __shared__ char smem[];
    float*  bsm = (float*)smem;                       // [128]
    __half* As  = (__half*)(smem + BIAS_BYTES);       // [128][ASTRIDE_H]
    __half* Bs  = (__half*)(smem + BS_OFF_B);         // [128 n][BSTRIDE_H]
    const int tid = threadIdx.x;
    const int wid = tid >> 5, lane = tid & 31;
    const int g = lane >> 2, tg = lane & 3;
    const int warp_m = wid & 3, warp_n = wid >> 2;
    const int base = blockIdx.x * 128;

    if (tid < 128) bsm[tid] = __ldg(&bias[tid]);

    // ---- stage B: straight uint4 copy of Wt (coalesced LDG, conflict-free STS) ----
    {
        const uint4* wt4 = (const uint4*)wt;          // 4096 uint4 (8 halves each)
        #pragma unroll
        for (int idx = tid; idx < 4096; idx += 256) {
            int n = idx >> 5, kq = idx & 31;          // kq: 8-half chunk along k
            *(uint4*)&Bs[n * BSTRIDE_H + kq * 8] = __ldg(&wt4[idx]);
        }
    }

    float c[2][8][4];
    #pragma unroll
    for (int mt = 0; mt < 2; mt++)
        #pragma unroll
        for (int nt = 0; nt < 8; nt++)
            #pragma unroll
            for (int q = 0; q < 4; q++) c[mt][nt][q] = 0.f;

    // ---- two K-passes: pass0 = self (k 0..127), pass1 = mean (k 128..255) ----
    #pragma unroll 1
    for (int pass = 0; pass < 2; pass++) {
        const uint4* srcA = (const uint4*)(pass ? aggh : selfh);  // 16B = 8 halves
        __syncthreads();   // previous-pass readers done before As overwrite
        #pragma unroll 8
        for (int idx = tid; idx < 2048; idx += 256) {     // 128 rows x 16 uint4
            int r = idx >> 4, q = idx & 15;
            int node = base + r;
            uint4 v = make_uint4(0u, 0u, 0u, 0u);
            if (node < NN) v = __ldg(&srcA[(size_t)node * 16 + q]);
            *(uint4*)&As[r * ASTRIDE_H + q * 8] = v;
        }
        __syncthreads();

        const __half* arow = &As[(warp_m * 32 + g) * ASTRIDE_H + 2 * tg];
        const __half* brow = &Bs[(warp_n * 64 + g) * BSTRIDE_H + 2 * tg + pass * 128];

        #pragma unroll
        for (int ks = 0; ks < 8; ks++) {                  // K = 128 per pass, k16 steps
            const int kb = ks * 16;
            uint32_t a[2][4];
            #pragma unroll
            for (int mt = 0; mt < 2; mt++) {
                const __half* p = arow + mt * 16 * ASTRIDE_H + kb;
                a[mt][0] = *(const uint32_t*)(p);
                a[mt][1] = *(const uint32_t*)(p + 8 * ASTRIDE_H);
                a[mt][2] = *(const uint32_t*)(p + 8);
                a[mt][3] = *(const uint32_t*)(p + 8 * ASTRIDE_H + 8);
            }
            uint32_t b[8][2];
            #pragma unroll
            for (int nt = 0; nt < 8; nt++) {
                const __half* p = brow + nt * 8 * BSTRIDE_H + kb;
                b[nt][0] = *(const uint32_t*)(p);
                b[nt][1] = *(const uint32_t*)(p + 8);
            }
            #pragma unroll
            for (int mt = 0; mt < 2; mt++)
                #pragma unroll
                for (int nt = 0; nt < 8; nt++)
                    MMA_F16(c[mt][nt], a[mt], b[nt]);
        }
    }

    // ---- epilogue: bias (+relu), fp32 and/or fp16 stores ----
    #pragma unroll
    for (int mt = 0; mt < 2; mt++) {
        #pragma unroll
        for (int half = 0; half < 2; half++) {
            int row = warp_m * 32 + mt * 16 + half * 8 + g;
            int node = base + row;
            if (node < NN) {
                #pragma unroll
                for (int nt = 0; nt < 8; nt++) {
                    int col = warp_n * 64 + nt * 8 + tg * 2;
                    float v0 = c[mt][nt][half * 2 + 0] + bsm[col];
                    float v1 = c[mt][nt][half * 2 + 1] + bsm[col + 1];
                    if (do_relu) { v0 = fmaxf(v0, 0.f); v1 = fmaxf(v1, 0.f); }
                    if (out_f)
                        *(float2*)(out_f + (size_t)node * 128 + col) = make_float2(v0, v1);
                    if (out_h) {
                        __half2 h = __floats2half2_rn(v0, v1);
                        *(__half2*)(out_h + (size_t)node * 128 + col) = h;
                    }
                }
            }
        }
    }
}

// ---------------- launch ----------------
extern "C" void kernel_launch(void* const* d_in, const int* in_sizes, int n_in,
                              void* d_out, int out_size) {
    const float* in_feat  = (const float*)d_in[0];
    const float* W1_self  = (const float*)d_in[1];
    const float* W1_neigh = (const float*)d_in[2];
    const float* b1       = (const float*)d_in[3];
    const float* W2_self  = (const float*)d_in[4];
    const float* W2_neigh = (const float*)d_in[5];
    const float* b2       = (const float*)d_in[6];
    const int*   src      = (const int*)d_in[7];
    const int*   dst      = (const int*)d_in[8];
    const int E = in_sizes[7];

    float* out = (float*)d_out;

    uint2 *xh, *h1h, *aggh;
    __half *wt1, *wt2;
    int *cnt, *off, *cur, *csrb;
    cudaGetSymbolAddress((void**)&xh,   g_xh);
    cudaGetSymbolAddress((void**)&h1h,  g_h1h);
    cudaGetSymbolAddress((void**)&aggh, g_aggh);
    cudaGetSymbolAddress((void**)&wt1,  g_wt1);
    cudaGetSymbolAddress((void**)&wt2,  g_wt2);
    cudaGetSymbolAddress((void**)&cnt,  g_cnt);
    cudaGetSymbolAddress((void**)&off,  g_off);
    cudaGetSymbolAddress((void**)&cur,  g_cur);
    cudaGetSymbolAddress((void**)&csrb, g_csrb);

    cudaFuncSetAttribute(layer_mma_kernel, cudaFuncAttributeMaxDynamicSharedMemorySize, SM_BYTES);

    const int eb4 = (E / 4 + 255) / 256;          // hist/fill blocks (4 edges/thread)
    const int pb  = CVT_BLOCKS + eb4 + 64;        // fused prep grid
    const int gb  = (NN * 32 + 255) / 256;        // warp per node
    const int lb  = (NN + 127) / 128;             // 128-node tiles

    // 1: fused prep (cvt + hist + wprep)
    prep_kernel<<<pb, 256>>>((const float4*)in_feat, xh, dst, cnt,
                             W1_self, W1_neigh, W2_self, W2_neigh, wt1, wt2, E, eb4);
    // 2: scan
    scan_kernel<<<1, SCAN_T>>>(cnt, off, cur);
    // 3: fill (+ cnt re-zero for next call)
    fill_kernel<<<eb4, 256>>>(src, dst, cur, csrb, cnt, E);
    // 4: gather layer 1  <-- profiled launch
    gather_kernel<<<gb, 256>>>((const char*)xh, off, csrb, (uint4*)aggh);
    // 5: layer 1
    layer_mma_kernel<<<lb, 256, SM_BYTES>>>(xh, aggh, wt1, b1,
                                            nullptr, (__half*)h1h, 1);
    // 6: gather layer 2
    gather_kernel<<<gb, 256>>>((const char*)h1h, off, csrb, (uint4*)aggh);
    // 7: layer 2
    layer_mma_kernel<<<lb, 256, SM_BYTES>>>(h1h, aggh, wt2, b2,
                                            out, nullptr, 0);
}